// round 5
// baseline (speedup 1.0000x reference)
#include <cuda_runtime.h>
#include <math.h>

#define NV 35709
#define NF 70789
#define NFP1 (NF + 1)
#define BATCH 32
#define M3 (3 * NV)   // 107127

// Output packing: face_color | landmark_p | fst
#define SZ_FC (BATCH * NV * 3)
#define OFF_FC 0
#define OFF_LM (SZ_FC)
#define SZ_LM (BATCH * 68 * 2)
#define OFF_FST (OFF_LM + SZ_LM)

// SH constants
#define C_Y0 0.8862269254527580f
#define C_Y1 1.7724538509055159f
#define C_Y4 2.4270324400f
#define C_Y6 0.7006239800f
#define C_Y8 1.2135162200f

// -------- scratch (device globals; no allocations allowed) --------
__device__ float4 g_fs[BATCH * NV];        // centered shape, xyz (+pad)
__device__ float4 g_fnorm[BATCH * NFP1];   // face normals (+ zero row at NF)
__device__ float  g_tex[BATCH * M3];       // texture, flat per batch
__device__ float  g_rot[BATCH * 9];        // rot = (Rz Ry Rx)^T, row-major
__device__ float  g_mean[3];               // mean of meanshape per coord (f32)
__device__ double g_mean_d[3];             // same in fp64

// ---------------------------------------------------------------------------
// Kernel A: meanshape mean (fp64, correctly rounded to f32) + rotations
// ---------------------------------------------------------------------------
__global__ void setup_kernel(const float* __restrict__ coeff,
                             const float* __restrict__ meanshape) {
    __shared__ double sx[256], sy[256], sz[256];
    int t = threadIdx.x;
    double ax = 0.0, ay = 0.0, az = 0.0;
    for (int i = t; i < NV; i += 256) {
        ax += (double)meanshape[3 * i + 0];
        ay += (double)meanshape[3 * i + 1];
        az += (double)meanshape[3 * i + 2];
    }
    sx[t] = ax; sy[t] = ay; sz[t] = az;
    __syncthreads();
    for (int s = 128; s > 0; s >>= 1) {
        if (t < s) { sx[t] += sx[t + s]; sy[t] += sy[t + s]; sz[t] += sz[t + s]; }
        __syncthreads();
    }
    if (t == 0) {
        g_mean_d[0] = sx[0] / (double)NV;
        g_mean_d[1] = sy[0] / (double)NV;
        g_mean_d[2] = sz[0] / (double)NV;
        g_mean[0] = (float)(sx[0] / (double)NV);
        g_mean[1] = (float)(sy[0] / (double)NV);
        g_mean[2] = (float)(sz[0] / (double)NV);
    }
    if (t < BATCH) {
        const float* c = coeff + t * 277;
        float ax0 = c[244], ay0 = c[245], az0 = c[246];
        float cx = cosf(ax0), sxr = sinf(ax0);
        float cy = cosf(ay0), syr = sinf(ay0);
        float cz = cosf(az0), szr = sinf(az0);
        float Rx[9] = {1, 0, 0,   0, cx, -sxr,   0, sxr, cx};
        float Ry[9] = {cy, 0, syr,   0, 1, 0,   -syr, 0, cy};
        float Rz[9] = {cz, -szr, 0,   szr, cz, 0,   0, 0, 1};
        float Tm[9], R[9];
        #pragma unroll
        for (int i = 0; i < 3; i++)
            #pragma unroll
            for (int j = 0; j < 3; j++) {
                float s = 0.f;
                #pragma unroll
                for (int k = 0; k < 3; k++) s += Rz[i * 3 + k] * Ry[k * 3 + j];
                Tm[i * 3 + j] = s;
            }
        #pragma unroll
        for (int i = 0; i < 3; i++)
            #pragma unroll
            for (int j = 0; j < 3; j++) {
                float s = 0.f;
                #pragma unroll
                for (int k = 0; k < 3; k++) s += Tm[i * 3 + k] * Rx[k * 3 + j];
                R[i * 3 + j] = s;
            }
        #pragma unroll
        for (int i = 0; i < 3; i++)
            #pragma unroll
            for (int j = 0; j < 3; j++)
                g_rot[t * 9 + i * 3 + j] = R[j * 3 + i];
    }
}

// ---------------------------------------------------------------------------
// Kernel B1: fs GEMM, REFERENCE-BIT-EXACT accumulation:
//   acc_id = k-ascending FMA chain over idBase (k=0..79, acc starts 0)
//   acc_ex = k-ascending FMA chain over exBase (k=0..63)
//   fs = rnd(rnd(acc_id + acc_ex) + meanshape) - mean       (XLA add order)
// This reproduces the per-element bit pattern of cublas-SGEMM / Eigen-gebp
// style k-serial single-accumulator chains that the reference einsums use.
// Exactness here is what makes the degenerate-face cross residuals (below)
// reproduce the reference's noise normals.
// ---------------------------------------------------------------------------
#define CSTRIDE 145
__global__ __launch_bounds__(256) void gemm_fs_kernel(
    const float* __restrict__ idBase, const float* __restrict__ exBase,
    const float* __restrict__ coeff, const float* __restrict__ meanshape) {
    __shared__ float Cs[BATCH * CSTRIDE];
    __shared__ float As[128 * 17];
    int t = threadIdx.x;
    int i0 = blockIdx.x * 128;

    for (int idx = t; idx < BATCH * 144; idx += 256) {
        int b = idx / 144, j = idx - b * 144;
        Cs[b * CSTRIDE + j] = coeff[b * 277 + j];
    }
    __syncthreads();

    int tx = t & 7;
    int ty = t >> 3;
    float acc80[4][4], acc64[4][4];
    #pragma unroll
    for (int r = 0; r < 4; r++)
        #pragma unroll
        for (int i = 0; i < 4; i++) { acc80[r][i] = 0.f; acc64[r][i] = 0.f; }

    // ---- idBase chunks: k0 = 0,16,32,48,64 (5 chunks, K=80) ----
    for (int k0 = 0; k0 < 80; k0 += 16) {
        #pragma unroll
        for (int j = 0; j < 8; j++) {
            int idx = t + 256 * j;
            int r = idx >> 4, kk = idx & 15;
            int row = i0 + r;
            As[r * 17 + kk] = (row < M3) ? idBase[(size_t)row * 80 + k0 + kk] : 0.f;
        }
        __syncthreads();
        #pragma unroll
        for (int kk = 0; kk < 16; kk++) {
            float a0 = As[(ty * 4 + 0) * 17 + kk];
            float a1 = As[(ty * 4 + 1) * 17 + kk];
            float a2 = As[(ty * 4 + 2) * 17 + kk];
            float a3 = As[(ty * 4 + 3) * 17 + kk];
            float b0 = Cs[(tx * 4 + 0) * CSTRIDE + k0 + kk];
            float b1 = Cs[(tx * 4 + 1) * CSTRIDE + k0 + kk];
            float b2 = Cs[(tx * 4 + 2) * CSTRIDE + k0 + kk];
            float b3 = Cs[(tx * 4 + 3) * CSTRIDE + k0 + kk];
            acc80[0][0] = __fmaf_rn(a0, b0, acc80[0][0]); acc80[0][1] = __fmaf_rn(a0, b1, acc80[0][1]);
            acc80[0][2] = __fmaf_rn(a0, b2, acc80[0][2]); acc80[0][3] = __fmaf_rn(a0, b3, acc80[0][3]);
            acc80[1][0] = __fmaf_rn(a1, b0, acc80[1][0]); acc80[1][1] = __fmaf_rn(a1, b1, acc80[1][1]);
            acc80[1][2] = __fmaf_rn(a1, b2, acc80[1][2]); acc80[1][3] = __fmaf_rn(a1, b3, acc80[1][3]);
            acc80[2][0] = __fmaf_rn(a2, b0, acc80[2][0]); acc80[2][1] = __fmaf_rn(a2, b1, acc80[2][1]);
            acc80[2][2] = __fmaf_rn(a2, b2, acc80[2][2]); acc80[2][3] = __fmaf_rn(a2, b3, acc80[2][3]);
            acc80[3][0] = __fmaf_rn(a3, b0, acc80[3][0]); acc80[3][1] = __fmaf_rn(a3, b1, acc80[3][1]);
            acc80[3][2] = __fmaf_rn(a3, b2, acc80[3][2]); acc80[3][3] = __fmaf_rn(a3, b3, acc80[3][3]);
        }
        __syncthreads();
    }
    // ---- exBase chunks: k0 = 80..143 (4 chunks, K=64) ----
    for (int k0 = 80; k0 < 144; k0 += 16) {
        #pragma unroll
        for (int j = 0; j < 8; j++) {
            int idx = t + 256 * j;
            int r = idx >> 4, kk = idx & 15;
            int row = i0 + r;
            As[r * 17 + kk] = (row < M3) ? exBase[(size_t)row * 64 + (k0 - 80) + kk] : 0.f;
        }
        __syncthreads();
        #pragma unroll
        for (int kk = 0; kk < 16; kk++) {
            float a0 = As[(ty * 4 + 0) * 17 + kk];
            float a1 = As[(ty * 4 + 1) * 17 + kk];
            float a2 = As[(ty * 4 + 2) * 17 + kk];
            float a3 = As[(ty * 4 + 3) * 17 + kk];
            float b0 = Cs[(tx * 4 + 0) * CSTRIDE + k0 + kk];
            float b1 = Cs[(tx * 4 + 1) * CSTRIDE + k0 + kk];
            float b2 = Cs[(tx * 4 + 2) * CSTRIDE + k0 + kk];
            float b3 = Cs[(tx * 4 + 3) * CSTRIDE + k0 + kk];
            acc64[0][0] = __fmaf_rn(a0, b0, acc64[0][0]); acc64[0][1] = __fmaf_rn(a0, b1, acc64[0][1]);
            acc64[0][2] = __fmaf_rn(a0, b2, acc64[0][2]); acc64[0][3] = __fmaf_rn(a0, b3, acc64[0][3]);
            acc64[1][0] = __fmaf_rn(a1, b0, acc64[1][0]); acc64[1][1] = __fmaf_rn(a1, b1, acc64[1][1]);
            acc64[1][2] = __fmaf_rn(a1, b2, acc64[1][2]); acc64[1][3] = __fmaf_rn(a1, b3, acc64[1][3]);
            acc64[2][0] = __fmaf_rn(a2, b0, acc64[2][0]); acc64[2][1] = __fmaf_rn(a2, b1, acc64[2][1]);
            acc64[2][2] = __fmaf_rn(a2, b2, acc64[2][2]); acc64[2][3] = __fmaf_rn(a2, b3, acc64[2][3]);
            acc64[3][0] = __fmaf_rn(a3, b0, acc64[3][0]); acc64[3][1] = __fmaf_rn(a3, b1, acc64[3][1]);
            acc64[3][2] = __fmaf_rn(a3, b2, acc64[3][2]); acc64[3][3] = __fmaf_rn(a3, b3, acc64[3][3]);
        }
        __syncthreads();
    }

    float* fsf = (float*)g_fs;
    #pragma unroll
    for (int r = 0; r < 4; r++) {
        int row = i0 + ty * 4 + r;
        if (row >= M3) continue;
        int v = row / 3;
        int c = row - 3 * v;
        float ms = meanshape[row];
        float mn = g_mean[c];
        #pragma unroll
        for (int i = 0; i < 4; i++) {
            int b = tx * 4 + i;
            float s = __fadd_rn(__fadd_rn(acc80[r][i], acc64[r][i]), ms);
            fsf[((size_t)b * NV + v) * 4 + c] = __fsub_rn(s, mn);
        }
    }
}

// ---------------------------------------------------------------------------
// Kernel B2: tex GEMM -> g_tex (multiplicative path; ulps don't amplify)
// ---------------------------------------------------------------------------
__global__ __launch_bounds__(256) void gemm_tex_kernel(
    const float* __restrict__ texBase, const float* __restrict__ coeff,
    const float* __restrict__ meantex) {
    __shared__ float Cs[BATCH * CSTRIDE];
    __shared__ float As[128 * 17];
    int t = threadIdx.x;
    int i0 = blockIdx.x * 128;

    for (int idx = t; idx < BATCH * 112; idx += 256) {
        int b = idx / 112, j = idx - b * 112;
        Cs[b * CSTRIDE + j] = (j < 100) ? coeff[b * 277 + 144 + j] : 0.f;
    }
    __syncthreads();

    int tx = t & 7;
    int ty = t >> 3;
    float acc[4][4];
    #pragma unroll
    for (int r = 0; r < 4; r++)
        #pragma unroll
        for (int i = 0; i < 4; i++) acc[r][i] = 0.f;

    for (int k0 = 0; k0 < 112; k0 += 16) {
        #pragma unroll
        for (int j = 0; j < 8; j++) {
            int idx = t + 256 * j;
            int r = idx >> 4, kk = idx & 15;
            int row = i0 + r;
            int k = k0 + kk;
            As[r * 17 + kk] = (row < M3 && k < 100) ? texBase[(size_t)row * 100 + k] : 0.f;
        }
        __syncthreads();
        #pragma unroll
        for (int kk = 0; kk < 16; kk++) {
            float a0 = As[(ty * 4 + 0) * 17 + kk];
            float a1 = As[(ty * 4 + 1) * 17 + kk];
            float a2 = As[(ty * 4 + 2) * 17 + kk];
            float a3 = As[(ty * 4 + 3) * 17 + kk];
            float b0 = Cs[(tx * 4 + 0) * CSTRIDE + k0 + kk];
            float b1 = Cs[(tx * 4 + 1) * CSTRIDE + k0 + kk];
            float b2 = Cs[(tx * 4 + 2) * CSTRIDE + k0 + kk];
            float b3 = Cs[(tx * 4 + 3) * CSTRIDE + k0 + kk];
            acc[0][0] += a0 * b0; acc[0][1] += a0 * b1; acc[0][2] += a0 * b2; acc[0][3] += a0 * b3;
            acc[1][0] += a1 * b0; acc[1][1] += a1 * b1; acc[1][2] += a1 * b2; acc[1][3] += a1 * b3;
            acc[2][0] += a2 * b0; acc[2][1] += a2 * b1; acc[2][2] += a2 * b2; acc[2][3] += a2 * b3;
            acc[3][0] += a3 * b0; acc[3][1] += a3 * b1; acc[3][2] += a3 * b2; acc[3][3] += a3 * b3;
        }
        __syncthreads();
    }

    #pragma unroll
    for (int r = 0; r < 4; r++) {
        int row = i0 + ty * 4 + r;
        if (row >= M3) continue;
        float mt = meantex[row];
        #pragma unroll
        for (int i = 0; i < 4; i++) {
            int b = tx * 4 + i;
            g_tex[(size_t)b * M3 + row] = acc[r][i] + mt;
        }
    }
}

// ---------------------------------------------------------------------------
// Kernel C: face normals — LLVM lhs-fuse contraction pattern:
//   c = fma(a_y, b_z, -rnd(a_z*b_y))   (first product fused, second plain mul)
// For the ~2 degenerate faces (i1==i3, so b = -a bitwise) this yields the
// rounding-residual noise vector the reference produces; with fs bits matched
// (kernel B1) the resulting noise normal matches the reference's.
// ---------------------------------------------------------------------------
__global__ __launch_bounds__(256) void facenorm_kernel(const int* __restrict__ face_buf) {
    int f = blockIdx.x * 256 + threadIdx.x;
    int b = blockIdx.y;
    if (f >= NFP1) return;
    float4* dst = g_fnorm + (size_t)b * NFP1 + f;
    if (f == NF) { *dst = make_float4(0.f, 0.f, 0.f, 0.f); return; }
    int i1 = face_buf[f * 3 + 0];
    int i2 = face_buf[f * 3 + 1];
    int i3 = face_buf[f * 3 + 2];
    const float4* fsb = g_fs + (size_t)b * NV;
    float4 p1 = fsb[i1], p2 = fsb[i2], p3 = fsb[i3];
    float e1x = __fsub_rn(p1.x, p2.x), e1y = __fsub_rn(p1.y, p2.y), e1z = __fsub_rn(p1.z, p2.z);
    float e2x = __fsub_rn(p2.x, p3.x), e2y = __fsub_rn(p2.y, p3.y), e2z = __fsub_rn(p2.z, p3.z);
    float cx = __fmaf_rn(e1y, e2z, -__fmul_rn(e1z, e2y));
    float cy = __fmaf_rn(e1z, e2x, -__fmul_rn(e1x, e2z));
    float cz = __fmaf_rn(e1x, e2y, -__fmul_rn(e1y, e2x));
    // norm: ascending sum of squares, exact f32 ops
    float n2 = __fadd_rn(__fadd_rn(__fmul_rn(cx, cx), __fmul_rn(cy, cy)), __fmul_rn(cz, cz));
    float len = sqrtf(n2);
    float d = fmaxf(len, 1e-12f);
    *dst = make_float4(__fdiv_rn(cx, d), __fdiv_rn(cy, d), __fdiv_rn(cz, d), 0.f);
}

// ---------------------------------------------------------------------------
// Kernel D: vertex normals -> rotate -> SH lighting -> face_color; fused fst
// ---------------------------------------------------------------------------
__global__ __launch_bounds__(256) void vertex_kernel(
    const int* __restrict__ point_buf, const float* __restrict__ coeff,
    float* __restrict__ out) {
    __shared__ float rot[9], trans[3], gsh[27];
    int b = blockIdx.y;
    int t = threadIdx.x;
    if (t < 9) rot[t] = g_rot[b * 9 + t];
    else if (t < 12) trans[t - 9] = coeff[b * 277 + 274 + (t - 9)];
    else if (t < 39) {
        int j = t - 12;
        gsh[j] = coeff[b * 277 + 247 + j] + (((j % 9) == 0) ? 0.8f : 0.f);
    }
    __syncthreads();
    int v = blockIdx.x * 256 + t;
    if (v >= NV) return;

    const int4* pb = (const int4*)point_buf;
    int4 q0 = pb[(size_t)v * 2 + 0];
    int4 q1 = pb[(size_t)v * 2 + 1];
    const float4* fn = g_fnorm + (size_t)b * NFP1;
    float nx = 0.f, ny = 0.f, nz = 0.f;
    float4 a;
    a = fn[q0.x]; nx += a.x; ny += a.y; nz += a.z;
    a = fn[q0.y]; nx += a.x; ny += a.y; nz += a.z;
    a = fn[q0.z]; nx += a.x; ny += a.y; nz += a.z;
    a = fn[q0.w]; nx += a.x; ny += a.y; nz += a.z;
    a = fn[q1.x]; nx += a.x; ny += a.y; nz += a.z;
    a = fn[q1.y]; nx += a.x; ny += a.y; nz += a.z;
    a = fn[q1.z]; nx += a.x; ny += a.y; nz += a.z;
    a = fn[q1.w]; nx += a.x; ny += a.y; nz += a.z;

    float len = sqrtf(nx * nx + ny * ny + nz * nz);
    float inv = 1.f / fmaxf(len, 1e-12f);
    nx *= inv; ny *= inv; nz *= inv;

    float rx = nx * rot[0] + ny * rot[3] + nz * rot[6];
    float ry = nx * rot[1] + ny * rot[4] + nz * rot[7];
    float rz = nx * rot[2] + ny * rot[5] + nz * rot[8];

    float Y[9];
    Y[0] = C_Y0;
    Y[1] = -C_Y1 * ry;
    Y[2] = C_Y1 * rz;
    Y[3] = -C_Y1 * rx;
    Y[4] = C_Y4 * rx * ry;
    Y[5] = -C_Y4 * ry * rz;
    Y[6] = C_Y6 * (3.f * rz * rz - 1.f);
    Y[7] = -C_Y4 * rx * rz;
    Y[8] = C_Y8 * (rx * rx - ny * 0.f - ry * ry);

    float lit[3];
    #pragma unroll
    for (int c = 0; c < 3; c++) {
        float s = 0.f;
        #pragma unroll
        for (int k = 0; k < 9; k++) s += Y[k] * gsh[c * 9 + k];
        lit[c] = s;
    }

    size_t base = (size_t)b * NV * 3 + (size_t)v * 3;
    const float* texv = g_tex + (size_t)b * M3 + (size_t)v * 3;
    out[OFF_FC + base + 0] = texv[0] * lit[0];
    out[OFF_FC + base + 1] = texv[1] * lit[1];
    out[OFF_FC + base + 2] = texv[2] * lit[2];

    float4 fs4 = g_fs[(size_t)b * NV + v];
    float fx = fs4.x * rot[0] + fs4.y * rot[3] + fs4.z * rot[6] + trans[0];
    float fy = fs4.x * rot[1] + fs4.y * rot[4] + fs4.z * rot[7] + trans[1];
    float fz = fs4.x * rot[2] + fs4.y * rot[5] + fs4.z * rot[8] + trans[2];
    out[OFF_FST + base + 0] = fx;
    out[OFF_FST + base + 1] = fy;
    out[OFF_FST + base + 2] = fz;
}

// ---------------------------------------------------------------------------
// Kernel E: landmarks in fp64 from raw inputs (division by Z ~ 0.01 amplifies;
// fp64 tracks the reference's value to its own rounding noise).
// ---------------------------------------------------------------------------
__global__ __launch_bounds__(128) void landmark_kernel(
    const float* __restrict__ idBase, const float* __restrict__ exBase,
    const float* __restrict__ meanshape, const float* __restrict__ coeff,
    const int* __restrict__ keypoints, float* __restrict__ out) {
    int idx = blockIdx.x * 128 + threadIdx.x;
    if (idx >= BATCH * 68) return;
    int b = idx / 68, l = idx - b * 68;
    int v = keypoints[l];
    const float* c = coeff + b * 277;

    double fs[3];
    #pragma unroll
    for (int cc = 0; cc < 3; cc++) {
        int row = 3 * v + cc;
        const float* idr = idBase + (size_t)row * 80;
        const float* exr = exBase + (size_t)row * 64;
        double s = 0.0;
        for (int k = 0; k < 80; k++) s += (double)idr[k] * (double)c[k];
        for (int k = 0; k < 64; k++) s += (double)exr[k] * (double)c[80 + k];
        fs[cc] = s + (double)meanshape[row] - g_mean_d[cc];
    }

    double ax0 = (double)c[244], ay0 = (double)c[245], az0 = (double)c[246];
    double cx = cos(ax0), sx = sin(ax0);
    double cy = cos(ay0), sy = sin(ay0);
    double cz = cos(az0), sz = sin(az0);
    double R[3][3];
    R[0][0] = cz * cy;  R[0][1] = cz * sy * sx - sz * cx;  R[0][2] = cz * sy * cx + sz * sx;
    R[1][0] = sz * cy;  R[1][1] = sz * sy * sx + cz * cx;  R[1][2] = sz * sy * cx - cz * sx;
    R[2][0] = -sy;      R[2][1] = cy * sx;                 R[2][2] = cy * cx;
    double fst[3];
    #pragma unroll
    for (int j = 0; j < 3; j++)
        fst[j] = fs[0] * R[j][0] + fs[1] * R[j][1] + fs[2] * R[j][2]
               + (double)c[274 + j];

    double Zc = 10.0 - fst[2];
    double lx = (1015.0 * fst[0] + 112.0 * Zc) / Zc;
    double ly = (1015.0 * fst[1] + 112.0 * Zc) / Zc;
    out[OFF_LM + (size_t)idx * 2 + 0] = (float)lx;
    out[OFF_LM + (size_t)idx * 2 + 1] = (float)ly;
}

// ---------------------------------------------------------------------------
extern "C" void kernel_launch(void* const* d_in, const int* in_sizes, int n_in,
                              void* d_out, int out_size) {
    const float* coeff     = (const float*)d_in[0];
    const float* idBase    = (const float*)d_in[1];
    const float* exBase    = (const float*)d_in[2];
    const float* texBase   = (const float*)d_in[3];
    const float* meanshape = (const float*)d_in[4];
    const float* meantex   = (const float*)d_in[5];
    const int*   face_buf  = (const int*)d_in[6];
    const int*   point_buf = (const int*)d_in[7];
    const int*   keypoints = (const int*)d_in[8];
    float* out = (float*)d_out;

    setup_kernel<<<1, 256>>>(coeff, meanshape);

    int gemm_blocks = (M3 + 127) / 128;
    gemm_fs_kernel<<<gemm_blocks, 256>>>(idBase, exBase, coeff, meanshape);
    gemm_tex_kernel<<<gemm_blocks, 256>>>(texBase, coeff, meantex);

    dim3 gc((NFP1 + 255) / 256, BATCH);
    facenorm_kernel<<<gc, 256>>>(face_buf);

    dim3 gv((NV + 255) / 256, BATCH);
    vertex_kernel<<<gv, 256>>>(point_buf, coeff, out);

    landmark_kernel<<<(BATCH * 68 + 127) / 128, 128>>>(
        idBase, exBase, meanshape, coeff, keypoints, out);
}

// round 7
// speedup vs baseline: 1.0993x; 1.0993x over previous
#include <cuda_runtime.h>
#include <math.h>

#define NV 35709
#define NF 70789
#define NFP1 (NF + 1)
#define BATCH 32
#define M3 (3 * NV)   // 107127
#define NV3 (NV * 3)

// Output packing: face_color | landmark_p | fst
#define SZ_FC (BATCH * NV * 3)
#define OFF_FC 0
#define OFF_LM (SZ_FC)
#define SZ_LM (BATCH * 68 * 2)
#define OFF_FST (OFF_LM + SZ_LM)

// SH constants
#define C_Y0 0.8862269254527580f
#define C_Y1 1.7724538509055159f
#define C_Y4 2.4270324400f
#define C_Y6 0.7006239800f
#define C_Y8 1.2135162200f

// -------- scratch (device globals; batch-innermost layouts) --------
__device__ float4 g_fs[NV * BATCH];        // [v][b] centered shape
__device__ float4 g_fnorm[NFP1 * BATCH];   // [f][b] face normals (+zero row)
__device__ float  g_tex[M3 * BATCH];       // [row][b] texture
__device__ float  g_rot[BATCH * 9];        // rot = (Rz Ry Rx)^T, row-major
__device__ float  g_mean[3];               // f32 mean (bits load-bearing)
__device__ double g_mean_d[3];

// ---------------------------------------------------------------------------
// Kernel A: meanshape mean (fp64) + rotations. UNCHANGED (bits load-bearing).
// ---------------------------------------------------------------------------
__global__ void setup_kernel(const float* __restrict__ coeff,
                             const float* __restrict__ meanshape) {
    __shared__ double sx[256], sy[256], sz[256];
    int t = threadIdx.x;
    double ax = 0.0, ay = 0.0, az = 0.0;
    for (int i = t; i < NV; i += 256) {
        ax += (double)meanshape[3 * i + 0];
        ay += (double)meanshape[3 * i + 1];
        az += (double)meanshape[3 * i + 2];
    }
    sx[t] = ax; sy[t] = ay; sz[t] = az;
    __syncthreads();
    for (int s = 128; s > 0; s >>= 1) {
        if (t < s) { sx[t] += sx[t + s]; sy[t] += sy[t + s]; sz[t] += sz[t + s]; }
        __syncthreads();
    }
    if (t == 0) {
        g_mean_d[0] = sx[0] / (double)NV;
        g_mean_d[1] = sy[0] / (double)NV;
        g_mean_d[2] = sz[0] / (double)NV;
        g_mean[0] = (float)(sx[0] / (double)NV);
        g_mean[1] = (float)(sy[0] / (double)NV);
        g_mean[2] = (float)(sz[0] / (double)NV);
    }
    if (t < BATCH) {
        const float* c = coeff + t * 277;
        float ax0 = c[244], ay0 = c[245], az0 = c[246];
        float cx = cosf(ax0), sxr = sinf(ax0);
        float cy = cosf(ay0), syr = sinf(ay0);
        float cz = cosf(az0), szr = sinf(az0);
        float Rx[9] = {1, 0, 0,   0, cx, -sxr,   0, sxr, cx};
        float Ry[9] = {cy, 0, syr,   0, 1, 0,   -syr, 0, cy};
        float Rz[9] = {cz, -szr, 0,   szr, cz, 0,   0, 0, 1};
        float Tm[9], R[9];
        #pragma unroll
        for (int i = 0; i < 3; i++)
            #pragma unroll
            for (int j = 0; j < 3; j++) {
                float s = 0.f;
                #pragma unroll
                for (int k = 0; k < 3; k++) s += Rz[i * 3 + k] * Ry[k * 3 + j];
                Tm[i * 3 + j] = s;
            }
        #pragma unroll
        for (int i = 0; i < 3; i++)
            #pragma unroll
            for (int j = 0; j < 3; j++) {
                float s = 0.f;
                #pragma unroll
                for (int k = 0; k < 3; k++) s += Tm[i * 3 + k] * Rx[k * 3 + j];
                R[i * 3 + j] = s;
            }
        #pragma unroll
        for (int i = 0; i < 3; i++)
            #pragma unroll
            for (int j = 0; j < 3; j++)
                g_rot[t * 9 + i * 3 + j] = R[j * 3 + i];
    }
}

// ---------------------------------------------------------------------------
// Kernel B1: fs GEMM — arithmetic UNCHANGED (bit-exact, load-bearing).
// Store layout [v][b].
// ---------------------------------------------------------------------------
#define CSTRIDE 145
__global__ __launch_bounds__(256) void gemm_fs_kernel(
    const float* __restrict__ idBase, const float* __restrict__ exBase,
    const float* __restrict__ coeff, const float* __restrict__ meanshape) {
    __shared__ float Cs[BATCH * CSTRIDE];
    __shared__ float As[128 * 17];
    int t = threadIdx.x;
    int i0 = blockIdx.x * 128;

    for (int idx = t; idx < BATCH * 144; idx += 256) {
        int b = idx / 144, j = idx - b * 144;
        Cs[b * CSTRIDE + j] = coeff[b * 277 + j];
    }
    __syncthreads();

    int tx = t & 7;
    int ty = t >> 3;
    float acc80[4][4], acc64[4][4];
    #pragma unroll
    for (int r = 0; r < 4; r++)
        #pragma unroll
        for (int i = 0; i < 4; i++) { acc80[r][i] = 0.f; acc64[r][i] = 0.f; }

    for (int k0 = 0; k0 < 80; k0 += 16) {
        #pragma unroll
        for (int j = 0; j < 8; j++) {
            int idx = t + 256 * j;
            int r = idx >> 4, kk = idx & 15;
            int row = i0 + r;
            As[r * 17 + kk] = (row < M3) ? idBase[(size_t)row * 80 + k0 + kk] : 0.f;
        }
        __syncthreads();
        #pragma unroll
        for (int kk = 0; kk < 16; kk++) {
            float a0 = As[(ty * 4 + 0) * 17 + kk];
            float a1 = As[(ty * 4 + 1) * 17 + kk];
            float a2 = As[(ty * 4 + 2) * 17 + kk];
            float a3 = As[(ty * 4 + 3) * 17 + kk];
            float b0 = Cs[(tx * 4 + 0) * CSTRIDE + k0 + kk];
            float b1 = Cs[(tx * 4 + 1) * CSTRIDE + k0 + kk];
            float b2 = Cs[(tx * 4 + 2) * CSTRIDE + k0 + kk];
            float b3 = Cs[(tx * 4 + 3) * CSTRIDE + k0 + kk];
            acc80[0][0] = __fmaf_rn(a0, b0, acc80[0][0]); acc80[0][1] = __fmaf_rn(a0, b1, acc80[0][1]);
            acc80[0][2] = __fmaf_rn(a0, b2, acc80[0][2]); acc80[0][3] = __fmaf_rn(a0, b3, acc80[0][3]);
            acc80[1][0] = __fmaf_rn(a1, b0, acc80[1][0]); acc80[1][1] = __fmaf_rn(a1, b1, acc80[1][1]);
            acc80[1][2] = __fmaf_rn(a1, b2, acc80[1][2]); acc80[1][3] = __fmaf_rn(a1, b3, acc80[1][3]);
            acc80[2][0] = __fmaf_rn(a2, b0, acc80[2][0]); acc80[2][1] = __fmaf_rn(a2, b1, acc80[2][1]);
            acc80[2][2] = __fmaf_rn(a2, b2, acc80[2][2]); acc80[2][3] = __fmaf_rn(a2, b3, acc80[2][3]);
            acc80[3][0] = __fmaf_rn(a3, b0, acc80[3][0]); acc80[3][1] = __fmaf_rn(a3, b1, acc80[3][1]);
            acc80[3][2] = __fmaf_rn(a3, b2, acc80[3][2]); acc80[3][3] = __fmaf_rn(a3, b3, acc80[3][3]);
        }
        __syncthreads();
    }
    for (int k0 = 80; k0 < 144; k0 += 16) {
        #pragma unroll
        for (int j = 0; j < 8; j++) {
            int idx = t + 256 * j;
            int r = idx >> 4, kk = idx & 15;
            int row = i0 + r;
            As[r * 17 + kk] = (row < M3) ? exBase[(size_t)row * 64 + (k0 - 80) + kk] : 0.f;
        }
        __syncthreads();
        #pragma unroll
        for (int kk = 0; kk < 16; kk++) {
            float a0 = As[(ty * 4 + 0) * 17 + kk];
            float a1 = As[(ty * 4 + 1) * 17 + kk];
            float a2 = As[(ty * 4 + 2) * 17 + kk];
            float a3 = As[(ty * 4 + 3) * 17 + kk];
            float b0 = Cs[(tx * 4 + 0) * CSTRIDE + k0 + kk];
            float b1 = Cs[(tx * 4 + 1) * CSTRIDE + k0 + kk];
            float b2 = Cs[(tx * 4 + 2) * CSTRIDE + k0 + kk];
            float b3 = Cs[(tx * 4 + 3) * CSTRIDE + k0 + kk];
            acc64[0][0] = __fmaf_rn(a0, b0, acc64[0][0]); acc64[0][1] = __fmaf_rn(a0, b1, acc64[0][1]);
            acc64[0][2] = __fmaf_rn(a0, b2, acc64[0][2]); acc64[0][3] = __fmaf_rn(a0, b3, acc64[0][3]);
            acc64[1][0] = __fmaf_rn(a1, b0, acc64[1][0]); acc64[1][1] = __fmaf_rn(a1, b1, acc64[1][1]);
            acc64[1][2] = __fmaf_rn(a1, b2, acc64[1][2]); acc64[1][3] = __fmaf_rn(a1, b3, acc64[1][3]);
            acc64[2][0] = __fmaf_rn(a2, b0, acc64[2][0]); acc64[2][1] = __fmaf_rn(a2, b1, acc64[2][1]);
            acc64[2][2] = __fmaf_rn(a2, b2, acc64[2][2]); acc64[2][3] = __fmaf_rn(a2, b3, acc64[2][3]);
            acc64[3][0] = __fmaf_rn(a3, b0, acc64[3][0]); acc64[3][1] = __fmaf_rn(a3, b1, acc64[3][1]);
            acc64[3][2] = __fmaf_rn(a3, b2, acc64[3][2]); acc64[3][3] = __fmaf_rn(a3, b3, acc64[3][3]);
        }
        __syncthreads();
    }

    float* fsf = (float*)g_fs;
    #pragma unroll
    for (int r = 0; r < 4; r++) {
        int row = i0 + ty * 4 + r;
        if (row >= M3) continue;
        int v = row / 3;
        int c = row - 3 * v;
        float ms = meanshape[row];
        float mn = g_mean[c];
        #pragma unroll
        for (int i = 0; i < 4; i++) {
            int b = tx * 4 + i;
            float s = __fadd_rn(__fadd_rn(acc80[r][i], acc64[r][i]), ms);
            fsf[((size_t)v * BATCH + b) * 4 + c] = __fsub_rn(s, mn);  // [v][b]
        }
    }
}

// ---------------------------------------------------------------------------
// Kernel B2: tex GEMM -> g_tex [row][b]
// ---------------------------------------------------------------------------
__global__ __launch_bounds__(256) void gemm_tex_kernel(
    const float* __restrict__ texBase, const float* __restrict__ coeff,
    const float* __restrict__ meantex) {
    __shared__ float Cs[BATCH * CSTRIDE];
    __shared__ float As[128 * 17];
    int t = threadIdx.x;
    int i0 = blockIdx.x * 128;

    for (int idx = t; idx < BATCH * 112; idx += 256) {
        int b = idx / 112, j = idx - b * 112;
        Cs[b * CSTRIDE + j] = (j < 100) ? coeff[b * 277 + 144 + j] : 0.f;
    }
    __syncthreads();

    int tx = t & 7;
    int ty = t >> 3;
    float acc[4][4];
    #pragma unroll
    for (int r = 0; r < 4; r++)
        #pragma unroll
        for (int i = 0; i < 4; i++) acc[r][i] = 0.f;

    for (int k0 = 0; k0 < 112; k0 += 16) {
        #pragma unroll
        for (int j = 0; j < 8; j++) {
            int idx = t + 256 * j;
            int r = idx >> 4, kk = idx & 15;
            int row = i0 + r;
            int k = k0 + kk;
            As[r * 17 + kk] = (row < M3 && k < 100) ? texBase[(size_t)row * 100 + k] : 0.f;
        }
        __syncthreads();
        #pragma unroll
        for (int kk = 0; kk < 16; kk++) {
            float a0 = As[(ty * 4 + 0) * 17 + kk];
            float a1 = As[(ty * 4 + 1) * 17 + kk];
            float a2 = As[(ty * 4 + 2) * 17 + kk];
            float a3 = As[(ty * 4 + 3) * 17 + kk];
            float b0 = Cs[(tx * 4 + 0) * CSTRIDE + k0 + kk];
            float b1 = Cs[(tx * 4 + 1) * CSTRIDE + k0 + kk];
            float b2 = Cs[(tx * 4 + 2) * CSTRIDE + k0 + kk];
            float b3 = Cs[(tx * 4 + 3) * CSTRIDE + k0 + kk];
            acc[0][0] += a0 * b0; acc[0][1] += a0 * b1; acc[0][2] += a0 * b2; acc[0][3] += a0 * b3;
            acc[1][0] += a1 * b0; acc[1][1] += a1 * b1; acc[1][2] += a1 * b2; acc[1][3] += a1 * b3;
            acc[2][0] += a2 * b0; acc[2][1] += a2 * b1; acc[2][2] += a2 * b2; acc[2][3] += a2 * b3;
            acc[3][0] += a3 * b0; acc[3][1] += a3 * b1; acc[3][2] += a3 * b2; acc[3][3] += a3 * b3;
        }
        __syncthreads();
    }

    #pragma unroll
    for (int r = 0; r < 4; r++) {
        int row = i0 + ty * 4 + r;
        if (row >= M3) continue;
        float mt = meantex[row];
        #pragma unroll
        for (int i = 0; i < 4; i++) {
            int b = tx * 4 + i;
            g_tex[(size_t)row * BATCH + b] = acc[r][i] + mt;  // [row][b]
        }
    }
}

// ---------------------------------------------------------------------------
// Kernel C: face normals — warp per face, lane = batch (coalesced 512B
// gathers). Arithmetic UNCHANGED (lhs-fuse cross is load-bearing).
// ---------------------------------------------------------------------------
__global__ __launch_bounds__(256) void facenorm_kernel(const int* __restrict__ face_buf) {
    int w = threadIdx.x >> 5;
    int lane = threadIdx.x & 31;
    int f = blockIdx.x * 8 + w;
    if (f > NF) return;
    float4* dst = g_fnorm + (size_t)f * BATCH + lane;
    if (f == NF) { *dst = make_float4(0.f, 0.f, 0.f, 0.f); return; }
    int i1 = face_buf[f * 3 + 0];
    int i2 = face_buf[f * 3 + 1];
    int i3 = face_buf[f * 3 + 2];
    float4 p1 = g_fs[(size_t)i1 * BATCH + lane];
    float4 p2 = g_fs[(size_t)i2 * BATCH + lane];
    float4 p3 = g_fs[(size_t)i3 * BATCH + lane];
    float e1x = __fsub_rn(p1.x, p2.x), e1y = __fsub_rn(p1.y, p2.y), e1z = __fsub_rn(p1.z, p2.z);
    float e2x = __fsub_rn(p2.x, p3.x), e2y = __fsub_rn(p2.y, p3.y), e2z = __fsub_rn(p2.z, p3.z);
    float cx = __fmaf_rn(e1y, e2z, -__fmul_rn(e1z, e2y));
    float cy = __fmaf_rn(e1z, e2x, -__fmul_rn(e1x, e2z));
    float cz = __fmaf_rn(e1x, e2y, -__fmul_rn(e1y, e2x));
    float n2 = __fadd_rn(__fadd_rn(__fmul_rn(cx, cx), __fmul_rn(cy, cy)), __fmul_rn(cz, cz));
    float len = sqrtf(n2);
    float d = fmaxf(len, 1e-12f);
    *dst = make_float4(__fdiv_rn(cx, d), __fdiv_rn(cy, d), __fdiv_rn(cz, d), 0.f);
}

// ---------------------------------------------------------------------------
// Kernel D: vertex pass — warp per vertex, lane = batch.
// FIX vs round 6: smem constant staging uses strided loops (BATCH*9 = 288
// exceeds the 256-thread block; round 6 left srot[256..287] = batches 28-31
// uninitialized -> rel_err 73).
// ---------------------------------------------------------------------------
__global__ __launch_bounds__(256) void vertex_kernel(
    const int* __restrict__ point_buf, const float* __restrict__ coeff,
    float* __restrict__ out) {
    __shared__ float srot[BATCH * 9];
    __shared__ float strans[BATCH * 3];
    __shared__ float sgsh[BATCH * 27];
    __shared__ float sfc[8 * BATCH * 3];
    __shared__ float sfst[8 * BATCH * 3];

    int t = threadIdx.x;
    for (int idx = t; idx < BATCH * 9; idx += 256) srot[idx] = g_rot[idx];
    for (int idx = t; idx < BATCH * 3; idx += 256)
        strans[idx] = coeff[(idx / 3) * 277 + 274 + (idx % 3)];
    for (int idx = t; idx < BATCH * 27; idx += 256) {
        int b = idx / 27, j = idx - b * 27;
        sgsh[idx] = coeff[b * 277 + 247 + j] + (((j % 9) == 0) ? 0.8f : 0.f);
    }
    __syncthreads();

    int w = t >> 5;
    int lane = t & 31;
    int v = blockIdx.x * 8 + w;

    if (v < NV) {
        const int4* pb = (const int4*)point_buf;
        int4 q0 = pb[(size_t)v * 2 + 0];
        int4 q1 = pb[(size_t)v * 2 + 1];
        const float4* fn = g_fnorm;
        float nx = 0.f, ny = 0.f, nz = 0.f;
        float4 a;
        a = fn[(size_t)q0.x * BATCH + lane]; nx += a.x; ny += a.y; nz += a.z;
        a = fn[(size_t)q0.y * BATCH + lane]; nx += a.x; ny += a.y; nz += a.z;
        a = fn[(size_t)q0.z * BATCH + lane]; nx += a.x; ny += a.y; nz += a.z;
        a = fn[(size_t)q0.w * BATCH + lane]; nx += a.x; ny += a.y; nz += a.z;
        a = fn[(size_t)q1.x * BATCH + lane]; nx += a.x; ny += a.y; nz += a.z;
        a = fn[(size_t)q1.y * BATCH + lane]; nx += a.x; ny += a.y; nz += a.z;
        a = fn[(size_t)q1.z * BATCH + lane]; nx += a.x; ny += a.y; nz += a.z;
        a = fn[(size_t)q1.w * BATCH + lane]; nx += a.x; ny += a.y; nz += a.z;

        float len = sqrtf(nx * nx + ny * ny + nz * nz);
        float inv = 1.f / fmaxf(len, 1e-12f);
        nx *= inv; ny *= inv; nz *= inv;

        const float* rot = srot + lane * 9;
        float rx = nx * rot[0] + ny * rot[3] + nz * rot[6];
        float ry = nx * rot[1] + ny * rot[4] + nz * rot[7];
        float rz = nx * rot[2] + ny * rot[5] + nz * rot[8];

        float Y[9];
        Y[0] = C_Y0;
        Y[1] = -C_Y1 * ry;
        Y[2] = C_Y1 * rz;
        Y[3] = -C_Y1 * rx;
        Y[4] = C_Y4 * rx * ry;
        Y[5] = -C_Y4 * ry * rz;
        Y[6] = C_Y6 * (3.f * rz * rz - 1.f);
        Y[7] = -C_Y4 * rx * rz;
        Y[8] = C_Y8 * (rx * rx - ry * ry);

        const float* gsh = sgsh + lane * 27;
        float lit[3];
        #pragma unroll
        for (int c = 0; c < 3; c++) {
            float s = 0.f;
            #pragma unroll
            for (int k = 0; k < 9; k++) s += Y[k] * gsh[c * 9 + k];
            lit[c] = s;
        }

        const float* texv = g_tex + (size_t)v * 3 * BATCH;
        float* fc = sfc + (w * BATCH + lane) * 3;
        fc[0] = texv[0 * BATCH + lane] * lit[0];
        fc[1] = texv[1 * BATCH + lane] * lit[1];
        fc[2] = texv[2 * BATCH + lane] * lit[2];

        float4 fs4 = g_fs[(size_t)v * BATCH + lane];
        const float* tr = strans + lane * 3;
        float* fo = sfst + (w * BATCH + lane) * 3;
        fo[0] = fs4.x * rot[0] + fs4.y * rot[3] + fs4.z * rot[6] + tr[0];
        fo[1] = fs4.x * rot[1] + fs4.y * rot[4] + fs4.z * rot[7] + tr[1];
        fo[2] = fs4.x * rot[2] + fs4.y * rot[5] + fs4.z * rot[8] + tr[2];
    }
    __syncthreads();

    // Write phase: batch b = t>>3, vertex-in-block wv = t&7; 3 floats each ->
    // per batch, 8 threads cover 96B contiguous in out.
    size_t v0 = (size_t)blockIdx.x * 8;
    int b = t >> 3;
    int wv = t & 7;
    if (v0 + wv < NV) {
        #pragma unroll
        for (int c = 0; c < 3; c++) {
            size_t go = (size_t)b * NV3 + (v0 + wv) * 3 + c;
            out[OFF_FC + go] = sfc[(wv * BATCH + b) * 3 + c];
            out[OFF_FST + go] = sfst[(wv * BATCH + b) * 3 + c];
        }
    }
}

// ---------------------------------------------------------------------------
// Kernel E: landmarks in fp64 from raw inputs. UNCHANGED.
// ---------------------------------------------------------------------------
__global__ __launch_bounds__(128) void landmark_kernel(
    const float* __restrict__ idBase, const float* __restrict__ exBase,
    const float* __restrict__ meanshape, const float* __restrict__ coeff,
    const int* __restrict__ keypoints, float* __restrict__ out) {
    int idx = blockIdx.x * 128 + threadIdx.x;
    if (idx >= BATCH * 68) return;
    int b = idx / 68, l = idx - b * 68;
    int v = keypoints[l];
    const float* c = coeff + b * 277;

    double fs[3];
    #pragma unroll
    for (int cc = 0; cc < 3; cc++) {
        int row = 3 * v + cc;
        const float* idr = idBase + (size_t)row * 80;
        const float* exr = exBase + (size_t)row * 64;
        double s = 0.0;
        for (int k = 0; k < 80; k++) s += (double)idr[k] * (double)c[k];
        for (int k = 0; k < 64; k++) s += (double)exr[k] * (double)c[80 + k];
        fs[cc] = s + (double)meanshape[row] - g_mean_d[cc];
    }

    double ax0 = (double)c[244], ay0 = (double)c[245], az0 = (double)c[246];
    double cx = cos(ax0), sx = sin(ax0);
    double cy = cos(ay0), sy = sin(ay0);
    double cz = cos(az0), sz = sin(az0);
    double R[3][3];
    R[0][0] = cz * cy;  R[0][1] = cz * sy * sx - sz * cx;  R[0][2] = cz * sy * cx + sz * sx;
    R[1][0] = sz * cy;  R[1][1] = sz * sy * sx + cz * cx;  R[1][2] = sz * sy * cx - cz * sx;
    R[2][0] = -sy;      R[2][1] = cy * sx;                 R[2][2] = cy * cx;
    double fst[3];
    #pragma unroll
    for (int j = 0; j < 3; j++)
        fst[j] = fs[0] * R[j][0] + fs[1] * R[j][1] + fs[2] * R[j][2]
               + (double)c[274 + j];

    double Zc = 10.0 - fst[2];
    double lx = (1015.0 * fst[0] + 112.0 * Zc) / Zc;
    double ly = (1015.0 * fst[1] + 112.0 * Zc) / Zc;
    out[OFF_LM + (size_t)idx * 2 + 0] = (float)lx;
    out[OFF_LM + (size_t)idx * 2 + 1] = (float)ly;
}

// ---------------------------------------------------------------------------
extern "C" void kernel_launch(void* const* d_in, const int* in_sizes, int n_in,
                              void* d_out, int out_size) {
    const float* coeff     = (const float*)d_in[0];
    const float* idBase    = (const float*)d_in[1];
    const float* exBase    = (const float*)d_in[2];
    const float* texBase   = (const float*)d_in[3];
    const float* meanshape = (const float*)d_in[4];
    const float* meantex   = (const float*)d_in[5];
    const int*   face_buf  = (const int*)d_in[6];
    const int*   point_buf = (const int*)d_in[7];
    const int*   keypoints = (const int*)d_in[8];
    float* out = (float*)d_out;

    setup_kernel<<<1, 256>>>(coeff, meanshape);

    int gemm_blocks = (M3 + 127) / 128;
    gemm_fs_kernel<<<gemm_blocks, 256>>>(idBase, exBase, coeff, meanshape);
    gemm_tex_kernel<<<gemm_blocks, 256>>>(texBase, coeff, meantex);

    facenorm_kernel<<<(NFP1 + 7) / 8, 256>>>(face_buf);

    vertex_kernel<<<(NV + 7) / 8, 256>>>(point_buf, coeff, out);

    landmark_kernel<<<(BATCH * 68 + 127) / 128, 128>>>(
        idBase, exBase, meanshape, coeff, keypoints, out);
}

// round 8
// speedup vs baseline: 1.4542x; 1.3229x over previous
#include <cuda_runtime.h>
#include <math.h>

#define NV 35709
#define NF 70789
#define NFP1 (NF + 1)
#define BATCH 32
#define M3 (3 * NV)   // 107127
#define NV3 (NV * 3)

// Output packing: face_color | landmark_p | fst
#define SZ_FC (BATCH * NV * 3)
#define OFF_FC 0
#define OFF_LM (SZ_FC)
#define SZ_LM (BATCH * 68 * 2)
#define OFF_FST (OFF_LM + SZ_LM)

// SH constants
#define C_Y0 0.8862269254527580f
#define C_Y1 1.7724538509055159f
#define C_Y4 2.4270324400f
#define C_Y6 0.7006239800f
#define C_Y8 1.2135162200f

// -------- scratch (device globals; batch-innermost layouts) --------
__device__ float4 g_fs[NV * BATCH];        // [v][b] centered shape
__device__ float4 g_fnorm[NFP1 * BATCH];   // [f][b] face normals (+zero row)
__device__ float  g_tex[M3 * BATCH];       // [row][b] texture
__device__ float  g_rot[BATCH * 9];        // rot = (Rz Ry Rx)^T, row-major
__device__ float  g_mean[3];               // f32 mean (bits load-bearing)
__device__ double g_mean_d[3];

// ---- f32x2 packed helpers (each half is an independent IEEE rn op) ----
__device__ __forceinline__ unsigned long long pack2(float x, float y) {
    unsigned long long r;
    asm("mov.b64 %0, {%1, %2};" : "=l"(r) : "f"(x), "f"(y));
    return r;
}
__device__ __forceinline__ void unpack2(unsigned long long v, float& x, float& y) {
    asm("mov.b64 {%0, %1}, %2;" : "=f"(x), "=f"(y) : "l"(v));
}
__device__ __forceinline__ unsigned long long fma2(
    unsigned long long a, unsigned long long b, unsigned long long c) {
    unsigned long long d;
    asm("fma.rn.f32x2 %0, %1, %2, %3;" : "=l"(d) : "l"(a), "l"(b), "l"(c));
    return d;
}

// ---------------------------------------------------------------------------
// Kernel A: meanshape mean (fp64) + rotations. 1024 threads (4x fewer serial
// iterations than 256). fp64 tree change shifts g_mean_d by ~1e-16 rel —
// far below f32 rounding, so g_mean f32 bits (load-bearing) are unchanged.
// ---------------------------------------------------------------------------
__global__ __launch_bounds__(1024) void setup_kernel(
    const float* __restrict__ coeff, const float* __restrict__ meanshape) {
    __shared__ double sx[1024], sy[1024], sz[1024];
    int t = threadIdx.x;
    double ax = 0.0, ay = 0.0, az = 0.0;
    for (int i = t; i < NV; i += 1024) {
        ax += (double)meanshape[3 * i + 0];
        ay += (double)meanshape[3 * i + 1];
        az += (double)meanshape[3 * i + 2];
    }
    sx[t] = ax; sy[t] = ay; sz[t] = az;
    __syncthreads();
    for (int s = 512; s > 0; s >>= 1) {
        if (t < s) { sx[t] += sx[t + s]; sy[t] += sy[t + s]; sz[t] += sz[t + s]; }
        __syncthreads();
    }
    if (t == 0) {
        g_mean_d[0] = sx[0] / (double)NV;
        g_mean_d[1] = sy[0] / (double)NV;
        g_mean_d[2] = sz[0] / (double)NV;
        g_mean[0] = (float)(sx[0] / (double)NV);
        g_mean[1] = (float)(sy[0] / (double)NV);
        g_mean[2] = (float)(sz[0] / (double)NV);
    }
    if (t < BATCH) {
        const float* c = coeff + t * 277;
        float ax0 = c[244], ay0 = c[245], az0 = c[246];
        float cx = cosf(ax0), sxr = sinf(ax0);
        float cy = cosf(ay0), syr = sinf(ay0);
        float cz = cosf(az0), szr = sinf(az0);
        float Rx[9] = {1, 0, 0,   0, cx, -sxr,   0, sxr, cx};
        float Ry[9] = {cy, 0, syr,   0, 1, 0,   -syr, 0, cy};
        float Rz[9] = {cz, -szr, 0,   szr, cz, 0,   0, 0, 1};
        float Tm[9], R[9];
        #pragma unroll
        for (int i = 0; i < 3; i++)
            #pragma unroll
            for (int j = 0; j < 3; j++) {
                float s = 0.f;
                #pragma unroll
                for (int k = 0; k < 3; k++) s += Rz[i * 3 + k] * Ry[k * 3 + j];
                Tm[i * 3 + j] = s;
            }
        #pragma unroll
        for (int i = 0; i < 3; i++)
            #pragma unroll
            for (int j = 0; j < 3; j++) {
                float s = 0.f;
                #pragma unroll
                for (int k = 0; k < 3; k++) s += Tm[i * 3 + k] * Rx[k * 3 + j];
                R[i * 3 + j] = s;
            }
        #pragma unroll
        for (int i = 0; i < 3; i++)
            #pragma unroll
            for (int j = 0; j < 3; j++)
                g_rot[t * 9 + i * 3 + j] = R[j * 3 + i];
    }
}

// ---------------------------------------------------------------------------
// Kernel B1: fs GEMM with f32x2 packed FMA. Each packed half is the SAME
// k-ascending rn-FMA chain as before -> per-element bits unchanged
// (load-bearing). Coeff tile transposed [k][b], stride 34 (8B-aligned,
// conflict-free), so batch-pairs load as one 64-bit LDS.
// ---------------------------------------------------------------------------
__global__ __launch_bounds__(256) void gemm_fs_kernel(
    const float* __restrict__ idBase, const float* __restrict__ exBase,
    const float* __restrict__ coeff, const float* __restrict__ meanshape) {
    __shared__ __align__(8) float Cs2[144 * 34];   // [k][b]
    __shared__ float As[128 * 17];
    int t = threadIdx.x;
    int i0 = blockIdx.x * 128;

    for (int idx = t; idx < BATCH * 144; idx += 256) {
        int b = idx / 144, j = idx - b * 144;
        Cs2[j * 34 + b] = coeff[b * 277 + j];
    }
    __syncthreads();

    int tx = t & 7;        // batch group: batches 4tx..4tx+3 (2 pairs)
    int ty = t >> 3;       // row group: rows ty*4..ty*4+3
    unsigned long long acc80[4][2], acc64[4][2];
    #pragma unroll
    for (int r = 0; r < 4; r++)
        #pragma unroll
        for (int p = 0; p < 2; p++) { acc80[r][p] = 0ULL; acc64[r][p] = 0ULL; }

    // ---- idBase chunks (K = 0..79) ----
    for (int k0 = 0; k0 < 80; k0 += 16) {
        #pragma unroll
        for (int j = 0; j < 8; j++) {
            int idx = t + 256 * j;
            int r = idx >> 4, kk = idx & 15;
            int row = i0 + r;
            As[r * 17 + kk] = (row < M3) ? idBase[(size_t)row * 80 + k0 + kk] : 0.f;
        }
        __syncthreads();
        #pragma unroll
        for (int kk = 0; kk < 16; kk++) {
            int k = k0 + kk;
            float a0 = As[(ty * 4 + 0) * 17 + kk];
            float a1 = As[(ty * 4 + 1) * 17 + kk];
            float a2 = As[(ty * 4 + 2) * 17 + kk];
            float a3 = As[(ty * 4 + 3) * 17 + kk];
            unsigned long long pa0 = pack2(a0, a0), pa1 = pack2(a1, a1);
            unsigned long long pa2 = pack2(a2, a2), pa3 = pack2(a3, a3);
            unsigned long long b01 = *reinterpret_cast<const unsigned long long*>(
                &Cs2[k * 34 + tx * 4]);
            unsigned long long b23 = *reinterpret_cast<const unsigned long long*>(
                &Cs2[k * 34 + tx * 4 + 2]);
            acc80[0][0] = fma2(pa0, b01, acc80[0][0]); acc80[0][1] = fma2(pa0, b23, acc80[0][1]);
            acc80[1][0] = fma2(pa1, b01, acc80[1][0]); acc80[1][1] = fma2(pa1, b23, acc80[1][1]);
            acc80[2][0] = fma2(pa2, b01, acc80[2][0]); acc80[2][1] = fma2(pa2, b23, acc80[2][1]);
            acc80[3][0] = fma2(pa3, b01, acc80[3][0]); acc80[3][1] = fma2(pa3, b23, acc80[3][1]);
        }
        __syncthreads();
    }
    // ---- exBase chunks (K = 80..143) ----
    for (int k0 = 80; k0 < 144; k0 += 16) {
        #pragma unroll
        for (int j = 0; j < 8; j++) {
            int idx = t + 256 * j;
            int r = idx >> 4, kk = idx & 15;
            int row = i0 + r;
            As[r * 17 + kk] = (row < M3) ? exBase[(size_t)row * 64 + (k0 - 80) + kk] : 0.f;
        }
        __syncthreads();
        #pragma unroll
        for (int kk = 0; kk < 16; kk++) {
            int k = k0 + kk;
            float a0 = As[(ty * 4 + 0) * 17 + kk];
            float a1 = As[(ty * 4 + 1) * 17 + kk];
            float a2 = As[(ty * 4 + 2) * 17 + kk];
            float a3 = As[(ty * 4 + 3) * 17 + kk];
            unsigned long long pa0 = pack2(a0, a0), pa1 = pack2(a1, a1);
            unsigned long long pa2 = pack2(a2, a2), pa3 = pack2(a3, a3);
            unsigned long long b01 = *reinterpret_cast<const unsigned long long*>(
                &Cs2[k * 34 + tx * 4]);
            unsigned long long b23 = *reinterpret_cast<const unsigned long long*>(
                &Cs2[k * 34 + tx * 4 + 2]);
            acc64[0][0] = fma2(pa0, b01, acc64[0][0]); acc64[0][1] = fma2(pa0, b23, acc64[0][1]);
            acc64[1][0] = fma2(pa1, b01, acc64[1][0]); acc64[1][1] = fma2(pa1, b23, acc64[1][1]);
            acc64[2][0] = fma2(pa2, b01, acc64[2][0]); acc64[2][1] = fma2(pa2, b23, acc64[2][1]);
            acc64[3][0] = fma2(pa3, b01, acc64[3][0]); acc64[3][1] = fma2(pa3, b23, acc64[3][1]);
        }
        __syncthreads();
    }

    float* fsf = (float*)g_fs;
    #pragma unroll
    for (int r = 0; r < 4; r++) {
        int row = i0 + ty * 4 + r;
        if (row >= M3) continue;
        int v = row / 3;
        int c = row - 3 * v;
        float ms = meanshape[row];
        float mn = g_mean[c];
        #pragma unroll
        for (int p = 0; p < 2; p++) {
            float lo80, hi80, lo64, hi64;
            unpack2(acc80[r][p], lo80, hi80);
            unpack2(acc64[r][p], lo64, hi64);
            int b = tx * 4 + 2 * p;
            float s0 = __fadd_rn(__fadd_rn(lo80, lo64), ms);
            fsf[((size_t)v * BATCH + b) * 4 + c] = __fsub_rn(s0, mn);
            float s1 = __fadd_rn(__fadd_rn(hi80, hi64), ms);
            fsf[((size_t)v * BATCH + b + 1) * 4 + c] = __fsub_rn(s1, mn);
        }
    }
}

// ---------------------------------------------------------------------------
// Kernel B2: tex GEMM, same f32x2 scheme -> g_tex [row][b]
// ---------------------------------------------------------------------------
__global__ __launch_bounds__(256) void gemm_tex_kernel(
    const float* __restrict__ texBase, const float* __restrict__ coeff,
    const float* __restrict__ meantex) {
    __shared__ __align__(8) float Cs2[112 * 34];
    __shared__ float As[128 * 17];
    int t = threadIdx.x;
    int i0 = blockIdx.x * 128;

    for (int idx = t; idx < BATCH * 112; idx += 256) {
        int b = idx / 112, j = idx - b * 112;
        Cs2[j * 34 + b] = (j < 100) ? coeff[b * 277 + 144 + j] : 0.f;
    }
    __syncthreads();

    int tx = t & 7;
    int ty = t >> 3;
    unsigned long long acc[4][2];
    #pragma unroll
    for (int r = 0; r < 4; r++)
        #pragma unroll
        for (int p = 0; p < 2; p++) acc[r][p] = 0ULL;

    for (int k0 = 0; k0 < 112; k0 += 16) {
        #pragma unroll
        for (int j = 0; j < 8; j++) {
            int idx = t + 256 * j;
            int r = idx >> 4, kk = idx & 15;
            int row = i0 + r;
            int k = k0 + kk;
            As[r * 17 + kk] = (row < M3 && k < 100) ? texBase[(size_t)row * 100 + k] : 0.f;
        }
        __syncthreads();
        #pragma unroll
        for (int kk = 0; kk < 16; kk++) {
            int k = k0 + kk;
            float a0 = As[(ty * 4 + 0) * 17 + kk];
            float a1 = As[(ty * 4 + 1) * 17 + kk];
            float a2 = As[(ty * 4 + 2) * 17 + kk];
            float a3 = As[(ty * 4 + 3) * 17 + kk];
            unsigned long long pa0 = pack2(a0, a0), pa1 = pack2(a1, a1);
            unsigned long long pa2 = pack2(a2, a2), pa3 = pack2(a3, a3);
            unsigned long long b01 = *reinterpret_cast<const unsigned long long*>(
                &Cs2[k * 34 + tx * 4]);
            unsigned long long b23 = *reinterpret_cast<const unsigned long long*>(
                &Cs2[k * 34 + tx * 4 + 2]);
            acc[0][0] = fma2(pa0, b01, acc[0][0]); acc[0][1] = fma2(pa0, b23, acc[0][1]);
            acc[1][0] = fma2(pa1, b01, acc[1][0]); acc[1][1] = fma2(pa1, b23, acc[1][1]);
            acc[2][0] = fma2(pa2, b01, acc[2][0]); acc[2][1] = fma2(pa2, b23, acc[2][1]);
            acc[3][0] = fma2(pa3, b01, acc[3][0]); acc[3][1] = fma2(pa3, b23, acc[3][1]);
        }
        __syncthreads();
    }

    #pragma unroll
    for (int r = 0; r < 4; r++) {
        int row = i0 + ty * 4 + r;
        if (row >= M3) continue;
        float mt = meantex[row];
        #pragma unroll
        for (int p = 0; p < 2; p++) {
            float lo, hi;
            unpack2(acc[r][p], lo, hi);
            int b = tx * 4 + 2 * p;
            g_tex[(size_t)row * BATCH + b] = lo + mt;
            g_tex[(size_t)row * BATCH + b + 1] = hi + mt;
        }
    }
}

// ---------------------------------------------------------------------------
// Kernel C: face normals — warp per 2 faces (6 gathers in flight; the round-7
// profile showed issue=47%, latency-bound). Arithmetic UNCHANGED (lhs-fuse
// cross is load-bearing).
// ---------------------------------------------------------------------------
__global__ __launch_bounds__(256) void facenorm_kernel(const int* __restrict__ face_buf) {
    int w = threadIdx.x >> 5;
    int lane = threadIdx.x & 31;
    int fbase = (blockIdx.x * 8 + w) * 2;
    #pragma unroll
    for (int u = 0; u < 2; u++) {
        int f = fbase + u;
        if (f > NF) continue;
        float4* dst = g_fnorm + (size_t)f * BATCH + lane;
        if (f == NF) { *dst = make_float4(0.f, 0.f, 0.f, 0.f); continue; }
        int i1 = face_buf[f * 3 + 0];
        int i2 = face_buf[f * 3 + 1];
        int i3 = face_buf[f * 3 + 2];
        float4 p1 = g_fs[(size_t)i1 * BATCH + lane];
        float4 p2 = g_fs[(size_t)i2 * BATCH + lane];
        float4 p3 = g_fs[(size_t)i3 * BATCH + lane];
        float e1x = __fsub_rn(p1.x, p2.x), e1y = __fsub_rn(p1.y, p2.y), e1z = __fsub_rn(p1.z, p2.z);
        float e2x = __fsub_rn(p2.x, p3.x), e2y = __fsub_rn(p2.y, p3.y), e2z = __fsub_rn(p2.z, p3.z);
        float cx = __fmaf_rn(e1y, e2z, -__fmul_rn(e1z, e2y));
        float cy = __fmaf_rn(e1z, e2x, -__fmul_rn(e1x, e2z));
        float cz = __fmaf_rn(e1x, e2y, -__fmul_rn(e1y, e2x));
        float n2 = __fadd_rn(__fadd_rn(__fmul_rn(cx, cx), __fmul_rn(cy, cy)), __fmul_rn(cz, cz));
        float len = sqrtf(n2);
        float d = fmaxf(len, 1e-12f);
        *dst = make_float4(__fdiv_rn(cx, d), __fdiv_rn(cy, d), __fdiv_rn(cz, d), 0.f);
    }
}

// ---------------------------------------------------------------------------
// Kernel D: vertex pass — warp per vertex, lane = batch. UNCHANGED from r7.
// ---------------------------------------------------------------------------
__global__ __launch_bounds__(256) void vertex_kernel(
    const int* __restrict__ point_buf, const float* __restrict__ coeff,
    float* __restrict__ out) {
    __shared__ float srot[BATCH * 9];
    __shared__ float strans[BATCH * 3];
    __shared__ float sgsh[BATCH * 27];
    __shared__ float sfc[8 * BATCH * 3];
    __shared__ float sfst[8 * BATCH * 3];

    int t = threadIdx.x;
    for (int idx = t; idx < BATCH * 9; idx += 256) srot[idx] = g_rot[idx];
    for (int idx = t; idx < BATCH * 3; idx += 256)
        strans[idx] = coeff[(idx / 3) * 277 + 274 + (idx % 3)];
    for (int idx = t; idx < BATCH * 27; idx += 256) {
        int b = idx / 27, j = idx - b * 27;
        sgsh[idx] = coeff[b * 277 + 247 + j] + (((j % 9) == 0) ? 0.8f : 0.f);
    }
    __syncthreads();

    int w = t >> 5;
    int lane = t & 31;
    int v = blockIdx.x * 8 + w;

    if (v < NV) {
        const int4* pb = (const int4*)point_buf;
        int4 q0 = pb[(size_t)v * 2 + 0];
        int4 q1 = pb[(size_t)v * 2 + 1];
        const float4* fn = g_fnorm;
        float nx = 0.f, ny = 0.f, nz = 0.f;
        float4 a;
        a = fn[(size_t)q0.x * BATCH + lane]; nx += a.x; ny += a.y; nz += a.z;
        a = fn[(size_t)q0.y * BATCH + lane]; nx += a.x; ny += a.y; nz += a.z;
        a = fn[(size_t)q0.z * BATCH + lane]; nx += a.x; ny += a.y; nz += a.z;
        a = fn[(size_t)q0.w * BATCH + lane]; nx += a.x; ny += a.y; nz += a.z;
        a = fn[(size_t)q1.x * BATCH + lane]; nx += a.x; ny += a.y; nz += a.z;
        a = fn[(size_t)q1.y * BATCH + lane]; nx += a.x; ny += a.y; nz += a.z;
        a = fn[(size_t)q1.z * BATCH + lane]; nx += a.x; ny += a.y; nz += a.z;
        a = fn[(size_t)q1.w * BATCH + lane]; nx += a.x; ny += a.y; nz += a.z;

        float len = sqrtf(nx * nx + ny * ny + nz * nz);
        float inv = 1.f / fmaxf(len, 1e-12f);
        nx *= inv; ny *= inv; nz *= inv;

        const float* rot = srot + lane * 9;
        float rx = nx * rot[0] + ny * rot[3] + nz * rot[6];
        float ry = nx * rot[1] + ny * rot[4] + nz * rot[7];
        float rz = nx * rot[2] + ny * rot[5] + nz * rot[8];

        float Y[9];
        Y[0] = C_Y0;
        Y[1] = -C_Y1 * ry;
        Y[2] = C_Y1 * rz;
        Y[3] = -C_Y1 * rx;
        Y[4] = C_Y4 * rx * ry;
        Y[5] = -C_Y4 * ry * rz;
        Y[6] = C_Y6 * (3.f * rz * rz - 1.f);
        Y[7] = -C_Y4 * rx * rz;
        Y[8] = C_Y8 * (rx * rx - ry * ry);

        const float* gsh = sgsh + lane * 27;
        float lit[3];
        #pragma unroll
        for (int c = 0; c < 3; c++) {
            float s = 0.f;
            #pragma unroll
            for (int k = 0; k < 9; k++) s += Y[k] * gsh[c * 9 + k];
            lit[c] = s;
        }

        const float* texv = g_tex + (size_t)v * 3 * BATCH;
        float* fc = sfc + (w * BATCH + lane) * 3;
        fc[0] = texv[0 * BATCH + lane] * lit[0];
        fc[1] = texv[1 * BATCH + lane] * lit[1];
        fc[2] = texv[2 * BATCH + lane] * lit[2];

        float4 fs4 = g_fs[(size_t)v * BATCH + lane];
        const float* tr = strans + lane * 3;
        float* fo = sfst + (w * BATCH + lane) * 3;
        fo[0] = fs4.x * rot[0] + fs4.y * rot[3] + fs4.z * rot[6] + tr[0];
        fo[1] = fs4.x * rot[1] + fs4.y * rot[4] + fs4.z * rot[7] + tr[1];
        fo[2] = fs4.x * rot[2] + fs4.y * rot[5] + fs4.z * rot[8] + tr[2];
    }
    __syncthreads();

    size_t v0 = (size_t)blockIdx.x * 8;
    int b = t >> 3;
    int wv = t & 7;
    if (v0 + wv < NV) {
        #pragma unroll
        for (int c = 0; c < 3; c++) {
            size_t go = (size_t)b * NV3 + (v0 + wv) * 3 + c;
            out[OFF_FC + go] = sfc[(wv * BATCH + b) * 3 + c];
            out[OFF_FST + go] = sfst[(wv * BATCH + b) * 3 + c];
        }
    }
}

// ---------------------------------------------------------------------------
// Kernel E: landmarks in fp64 from raw inputs. UNCHANGED.
// ---------------------------------------------------------------------------
__global__ __launch_bounds__(128) void landmark_kernel(
    const float* __restrict__ idBase, const float* __restrict__ exBase,
    const float* __restrict__ meanshape, const float* __restrict__ coeff,
    const int* __restrict__ keypoints, float* __restrict__ out) {
    int idx = blockIdx.x * 128 + threadIdx.x;
    if (idx >= BATCH * 68) return;
    int b = idx / 68, l = idx - b * 68;
    int v = keypoints[l];
    const float* c = coeff + b * 277;

    double fs[3];
    #pragma unroll
    for (int cc = 0; cc < 3; cc++) {
        int row = 3 * v + cc;
        const float* idr = idBase + (size_t)row * 80;
        const float* exr = exBase + (size_t)row * 64;
        double s = 0.0;
        for (int k = 0; k < 80; k++) s += (double)idr[k] * (double)c[k];
        for (int k = 0; k < 64; k++) s += (double)exr[k] * (double)c[80 + k];
        fs[cc] = s + (double)meanshape[row] - g_mean_d[cc];
    }

    double ax0 = (double)c[244], ay0 = (double)c[245], az0 = (double)c[246];
    double cx = cos(ax0), sx = sin(ax0);
    double cy = cos(ay0), sy = sin(ay0);
    double cz = cos(az0), sz = sin(az0);
    double R[3][3];
    R[0][0] = cz * cy;  R[0][1] = cz * sy * sx - sz * cx;  R[0][2] = cz * sy * cx + sz * sx;
    R[1][0] = sz * cy;  R[1][1] = sz * sy * sx + cz * cx;  R[1][2] = sz * sy * cx - cz * sx;
    R[2][0] = -sy;      R[2][1] = cy * sx;                 R[2][2] = cy * cx;
    double fst[3];
    #pragma unroll
    for (int j = 0; j < 3; j++)
        fst[j] = fs[0] * R[j][0] + fs[1] * R[j][1] + fs[2] * R[j][2]
               + (double)c[274 + j];

    double Zc = 10.0 - fst[2];
    double lx = (1015.0 * fst[0] + 112.0 * Zc) / Zc;
    double ly = (1015.0 * fst[1] + 112.0 * Zc) / Zc;
    out[OFF_LM + (size_t)idx * 2 + 0] = (float)lx;
    out[OFF_LM + (size_t)idx * 2 + 1] = (float)ly;
}

// ---------------------------------------------------------------------------
// Launcher with fork-join stream overlap (graph-capturable: all cross-stream
// deps via events; streams/events lazily created OUTSIDE capture on the first
// (correctness) call; identical work every call).
//   main:  setup -> gemm_fs -> facenorm -> [wait tex] vertex -> [wait lm]
//   s2:    gemm_tex                       (no deps)
//   s3:    [wait setup] landmark          (needs g_mean_d)
// ---------------------------------------------------------------------------
extern "C" void kernel_launch(void* const* d_in, const int* in_sizes, int n_in,
                              void* d_out, int out_size) {
    const float* coeff     = (const float*)d_in[0];
    const float* idBase    = (const float*)d_in[1];
    const float* exBase    = (const float*)d_in[2];
    const float* texBase   = (const float*)d_in[3];
    const float* meanshape = (const float*)d_in[4];
    const float* meantex   = (const float*)d_in[5];
    const int*   face_buf  = (const int*)d_in[6];
    const int*   point_buf = (const int*)d_in[7];
    const int*   keypoints = (const int*)d_in[8];
    float* out = (float*)d_out;

    static cudaStream_t s2 = 0, s3 = 0;
    static cudaEvent_t evO = 0, evS = 0, evT = 0, evL = 0;
    if (!s2) {
        cudaStreamCreateWithFlags(&s2, cudaStreamNonBlocking);
        cudaStreamCreateWithFlags(&s3, cudaStreamNonBlocking);
        cudaEventCreateWithFlags(&evO, cudaEventDisableTiming);
        cudaEventCreateWithFlags(&evS, cudaEventDisableTiming);
        cudaEventCreateWithFlags(&evT, cudaEventDisableTiming);
        cudaEventCreateWithFlags(&evL, cudaEventDisableTiming);
    }

    int gemm_blocks = (M3 + 127) / 128;

    // fork point
    cudaEventRecord(evO, 0);
    cudaStreamWaitEvent(s2, evO, 0);
    cudaStreamWaitEvent(s3, evO, 0);

    // s2: tex GEMM (independent of everything)
    gemm_tex_kernel<<<gemm_blocks, 256, 0, s2>>>(texBase, coeff, meantex);
    cudaEventRecord(evT, s2);

    // main: setup -> fs GEMM -> facenorm
    setup_kernel<<<1, 1024>>>(coeff, meanshape);
    cudaEventRecord(evS, 0);
    gemm_fs_kernel<<<gemm_blocks, 256>>>(idBase, exBase, coeff, meanshape);
    facenorm_kernel<<<(NFP1 + 15) / 16, 256>>>(face_buf);

    // s3: landmark (needs setup's g_mean_d)
    cudaStreamWaitEvent(s3, evS, 0);
    landmark_kernel<<<(BATCH * 68 + 127) / 128, 128, 0, s3>>>(
        idBase, exBase, meanshape, coeff, keypoints, out);
    cudaEventRecord(evL, s3);

    // join: vertex needs tex + facenorm (+rot via stream order)
    cudaStreamWaitEvent(0, evT, 0);
    vertex_kernel<<<(NV + 7) / 8, 256>>>(point_buf, coeff, out);
    cudaStreamWaitEvent(0, evL, 0);
}